// round 8
// baseline (speedup 1.0000x reference)
#include <cuda_runtime.h>
#include <math.h>
#include <stdint.h>

typedef unsigned int u32;

// ---------------------------------------------------------------------------
// Problem constants
// ---------------------------------------------------------------------------
constexpr int B_    = 16;
constexpr int C_    = 256;
constexpr int L_    = 2048;
constexpr int ZD_   = 128;
constexpr int TEMB_ = 512;
constexpr size_t BCL = (size_t)B_ * C_ * L_;
constexpr size_t BLL = (size_t)B_ * L_ * L_;

// ---------------------------------------------------------------------------
// Scratch (device globals; allocation-free per harness rules)
// ---------------------------------------------------------------------------
__device__ float  g_h  [BCL];                    // conv1 output
__device__ float  g_x1 [BCL];                    // x + conv2(...)
__device__ float  g_hnT[BCL];                    // norm(x1) transposed [B][L][C] (tf32)
__device__ float  g_qk [(size_t)B_ * L_ * 512];  // q|k fused: [B][L][512] (tf32)
__device__ float  g_v  [BCL];                    // v   [B][C][L] (tf32)
__device__ float  g_h2T[BCL];                    // attn out [B][L][C] (tf32)
__device__ float  g_sc [BLL];                    // scores fp32 / softmax out (tf32)
__device__ float  g_add[B_ * C_];                // temb/z projection vector
__device__ float2 g_st [B_ * C_];                // per-row norm fold (fA, fB), reused
// tf32-pre-rounded weights: qk(512x256) | vw | pw | c1w | c2w ; then qk bias
__device__ float g_wr[512 * C_ + 2 * C_ * C_ + 2 * C_ * C_ * 3 + 512];

static __device__ __forceinline__ float silu_f(float x) {
    return x / (1.f + expf(-x));
}

static __device__ __forceinline__ float f2tf_f(float x) {
    u32 r;
    asm("cvt.rna.tf32.f32 %0, %1;" : "=r"(r) : "f"(x));
    return __uint_as_float(r);
}

#define MMA_TF32(d, a, b)                                                     \
    asm volatile("mma.sync.aligned.m16n8k8.row.col.f32.tf32.tf32.f32 "       \
                 "{%0,%1,%2,%3},{%4,%5,%6,%7},{%8,%9},{%0,%1,%2,%3};"         \
                 : "+f"(d[0]), "+f"(d[1]), "+f"(d[2]), "+f"(d[3])             \
                 : "r"(a[0]), "r"(a[1]), "r"(a[2]), "r"(a[3]),                \
                   "r"(b[0]), "r"(b[1]))

// ---------------------------------------------------------------------------
// Weight prep kernels (tiny, run once per launch)
// ---------------------------------------------------------------------------
__global__ void round_tf32_kernel(const float* __restrict__ in,
                                  float* __restrict__ out, int n)
{
    int i = blockIdx.x * 256 + threadIdx.x;
    if (i < n) out[i] = f2tf_f(in[i]);
}

// concat qw|kw rows (512x256) + qb|kb (512), tf32-round weights
__global__ void round_concat_qk(const float* __restrict__ qw,
                                const float* __restrict__ kw,
                                const float* __restrict__ qb,
                                const float* __restrict__ kb,
                                float* __restrict__ wdst,
                                float* __restrict__ bdst)
{
    int i = blockIdx.x * 256 + threadIdx.x;
    int total = 512 * C_;
    if (i < total) {
        int n = i >> 8;   // /256
        wdst[i] = f2tf_f(n < C_ ? qw[i] : kw[i - C_ * C_]);
    }
    if (i < 512) bdst[i] = (i < C_) ? qb[i] : kb[i - C_];
}

// ---------------------------------------------------------------------------
// Kernel: timestep embedding MLP + fused add-vector
// ---------------------------------------------------------------------------
__global__ void temb_kernel(const int* __restrict__ t,
                            const float* __restrict__ z0,
                            const float* __restrict__ zt,
                            const float* __restrict__ tw1, const float* __restrict__ tb1,
                            const float* __restrict__ tw2, const float* __restrict__ tb2,
                            const float* __restrict__ tpw, const float* __restrict__ tpb,
                            const float* __restrict__ zpw, const float* __restrict__ zpb)
{
    __shared__ float se[128];
    __shared__ float s1[512];
    __shared__ float s2[512];
    __shared__ float sz[256];

    int b = blockIdx.x, tid = threadIdx.x;

    if (tid < 64) {
        float f = expf((float)tid * (-logf(10000.f) / 63.f));
        float a = (float)t[b] * f;
        se[tid]      = sinf(a);
        se[64 + tid] = cosf(a);
    }
    if (tid < 128) {
        sz[tid]       = silu_f(z0[b * ZD_ + tid]);
        sz[128 + tid] = silu_f(zt[b * ZD_ + tid]);
    }
    __syncthreads();

    {
        float acc = tb1[tid];
        #pragma unroll 8
        for (int i = 0; i < 128; i++) acc += se[i] * tw1[i * TEMB_ + tid];
        s1[tid] = silu_f(acc);
    }
    __syncthreads();
    {
        float acc = tb2[tid];
        #pragma unroll 8
        for (int k = 0; k < 512; k++) acc += s1[k] * tw2[k * TEMB_ + tid];
        s2[tid] = silu_f(acc);
    }
    __syncthreads();

    if (tid < C_) {
        float acc = tpb[tid] + 2.f * zpb[tid];
        #pragma unroll 8
        for (int j = 0; j < 512; j++) acc += s2[j] * tpw[j * C_ + tid];
        #pragma unroll 8
        for (int i = 0; i < 128; i++) acc += (sz[i] + sz[128 + i]) * zpw[i * C_ + tid];
        g_add[b * C_ + tid] = acc;
    }
}

// ---------------------------------------------------------------------------
// Kernel: per-(b,c) norm statistics -> fold factors (fA, fB).
//   y = x*fA + fB  ==  (x - mean) * rstd * gamma + beta
// float4 loads, one block (256 thr) per row.
// ---------------------------------------------------------------------------
__global__ __launch_bounds__(256) void stats_kernel(const float* __restrict__ in,
                                                    const float* __restrict__ gam,
                                                    const float* __restrict__ bet,
                                                    float2* __restrict__ st)
{
    __shared__ float red[64];
    int row = blockIdx.x, tid = threadIdx.x;
    const float4* p4 = (const float4*)(in + (size_t)row * L_);

    float4 a = p4[tid];
    float4 b = p4[tid + 256];
    float s  = a.x + a.y + a.z + a.w + b.x + b.y + b.z + b.w;
    float sq = a.x * a.x + a.y * a.y + a.z * a.z + a.w * a.w
             + b.x * b.x + b.y * b.y + b.z * b.z + b.w * b.w;

    #pragma unroll
    for (int o = 16; o > 0; o >>= 1) {
        s  += __shfl_down_sync(0xffffffffu, s,  o);
        sq += __shfl_down_sync(0xffffffffu, sq, o);
    }
    if ((tid & 31) == 0) { red[tid >> 5] = s; red[8 + (tid >> 5)] = sq; }
    __syncthreads();
    if (tid == 0) {
        float S = 0.f, SQ = 0.f;
        #pragma unroll
        for (int i = 0; i < 8; i++) { S += red[i]; SQ += red[8 + i]; }
        float mean = S * (1.f / L_);
        float var  = SQ * (1.f / L_) - mean * mean;
        float rstd = rsqrtf(var + 1e-6f);
        int c = row & (C_ - 1);
        float fA = rstd * gam[c];
        st[row] = make_float2(fA, bet[c] - mean * fA);
    }
}

// ---------------------------------------------------------------------------
// Kernel: fused norm + 32x32 transpose, [B][C][L] -> [B][L][C], tf32 out.
// ---------------------------------------------------------------------------
__global__ __launch_bounds__(256) void transpose_norm(const float* __restrict__ in,
                                                      const float2* __restrict__ st,
                                                      float* __restrict__ out)
{
    __shared__ float tile[32][33];
    int b = blockIdx.z;
    int l0 = blockIdx.x * 32, c0 = blockIdx.y * 32;
    int tx = threadIdx.x & 31, ty = threadIdx.x >> 5;
    #pragma unroll
    for (int i = 0; i < 4; i++) {
        int c = c0 + ty + i * 8;
        float2 f = st[b * C_ + c];
        float x = in[((size_t)(b * C_ + c)) * L_ + l0 + tx];
        tile[ty + i * 8][tx] = f2tf_f(fmaf(x, f.x, f.y));
    }
    __syncthreads();
    #pragma unroll
    for (int i = 0; i < 4; i++) {
        int l = l0 + ty + i * 8;
        out[((size_t)b * L_ + l) * C_ + c0 + tx] = tile[tx][ty + i * 8];
    }
}

// ---------------------------------------------------------------------------
// tf32 tensor-core GEMM — k-tile 32, static 36KB smem, 2 CTAs/SM forced.
//   C[m][n] = alpha * sum_k A[m][k] * B[n][k]  (generalized lda/ldb/ldc)
// Operands MUST be tf32-representable (pre-rounded).
// BIAS_MODE: 0 none, 1 per-m, 2 per-n. RES: fp32 residual. OTF32: round out.
// ---------------------------------------------------------------------------
template <int BIAS_MODE, bool RES, bool OTF32>
__global__ __launch_bounds__(256, 2) void gemm_tf32(
    const float* __restrict__ A, const float* __restrict__ Bm,
    const float* __restrict__ bias, const float* __restrict__ res,
    float* __restrict__ Cout, int K, int lda, int ldb, int ldc,
    float alpha, size_t strideA, size_t strideB, size_t strideC)
{
    __shared__ float sA[128][36];
    __shared__ float sB[128][36];

    int bz = blockIdx.z;
    A  += strideA * bz;
    Bm += strideB * bz;

    int m0 = blockIdx.y * 128, n0 = blockIdx.x * 128;
    int tid = threadIdx.x, lane = tid & 31, w = tid >> 5;
    int wm = (w & 3) * 32, wn = (w >> 2) * 64;
    int g = lane >> 2, tg = lane & 3;

    float acc[2][8][4] = {};

    for (int k0 = 0; k0 < K; k0 += 32) {
        __syncthreads();
        #pragma unroll
        for (int it = 0; it < 4; it++) {
            int idx = tid + it * 256;
            int row = idx >> 3, seg = (idx & 7) * 4;
            *(float4*)&sA[row][seg] =
                *(const float4*)&A[(size_t)(m0 + row) * lda + k0 + seg];
            *(float4*)&sB[row][seg] =
                *(const float4*)&Bm[(size_t)(n0 + row) * ldb + k0 + seg];
        }
        __syncthreads();

        #pragma unroll
        for (int ks = 0; ks < 4; ks++) {
            int kb = ks * 8 + tg;
            u32 afr[2][4], bfr[8][2];
            #pragma unroll
            for (int mt = 0; mt < 2; mt++) {
                int r = wm + mt * 16 + g;
                afr[mt][0] = __float_as_uint(sA[r][kb]);
                afr[mt][1] = __float_as_uint(sA[r + 8][kb]);
                afr[mt][2] = __float_as_uint(sA[r][kb + 4]);
                afr[mt][3] = __float_as_uint(sA[r + 8][kb + 4]);
            }
            #pragma unroll
            for (int nt = 0; nt < 8; nt++) {
                int c = wn + nt * 8 + g;
                bfr[nt][0] = __float_as_uint(sB[c][kb]);
                bfr[nt][1] = __float_as_uint(sB[c][kb + 4]);
            }
            #pragma unroll
            for (int mt = 0; mt < 2; mt++)
                #pragma unroll
                for (int nt = 0; nt < 8; nt++)
                    MMA_TF32(acc[mt][nt], afr[mt], bfr[nt]);
        }
    }

    // epilogue
    #pragma unroll
    for (int mt = 0; mt < 2; mt++) {
        #pragma unroll
        for (int half = 0; half < 2; half++) {
            int m = m0 + wm + mt * 16 + g + half * 8;
            float bm = (BIAS_MODE == 1) ? bias[m] : 0.f;
            #pragma unroll
            for (int nt = 0; nt < 8; nt++) {
                int n = n0 + wn + nt * 8 + tg * 2;
                float v0 = acc[mt][nt][half * 2 + 0] * alpha;
                float v1 = acc[mt][nt][half * 2 + 1] * alpha;
                if (BIAS_MODE == 1) { v0 += bm; v1 += bm; }
                if (BIAS_MODE == 2) { v0 += bias[n]; v1 += bias[n + 1]; }
                size_t off = strideC * bz + (size_t)m * ldc + n;
                if (RES) {
                    float2 r2 = *(const float2*)&res[off];
                    v0 += r2.x; v1 += r2.y;
                }
                if (OTF32) { v0 = f2tf_f(v0); v1 = f2tf_f(v1); }
                *(float2*)&Cout[off] = make_float2(v0, v1);
            }
        }
    }
}

// ---------------------------------------------------------------------------
// tf32 tensor-core 3-tap conv (implicit GEMM) with FUSED norm+silu on the
// input loader: v = tf32(silu(x*fA + fB)), zero padding preserved.
// Weights pre-rounded. 2 CTAs/SM forced.
// M=C (co), N=L(128-tile), K=768 in 16 chunks of 48 (16 ci x 3 taps).
// ---------------------------------------------------------------------------
constexpr int CONV_SMEM = 2 * 128 * 52 * 4;   // 53248 B (dynamic, 2 CTAs/SM)

template <bool ADDV, bool RES>
__global__ __launch_bounds__(256, 2) void conv_tf32(
    const float* __restrict__ in,   // [B][C][L] RAW (pre-norm) values
    const float2* __restrict__ st,  // per-(b,c) fold factors
    const float* __restrict__ w,    // [C][768]  (tf32 values)
    const float* __restrict__ bias,
    const float* __restrict__ addv,
    const float* __restrict__ resid,
    float* __restrict__ out)
{
    extern __shared__ float smemc[];
    float (*sA)[52] = (float(*)[52])smemc;              // weights [co][48]
    float (*sB)[52] = (float(*)[52])(smemc + 128 * 52); // patch   [l][48]

    int b  = blockIdx.z;
    int m0 = blockIdx.y * 128;
    int l0 = blockIdx.x * 128;
    int tid = threadIdx.x, lane = tid & 31, wid = tid >> 5;
    int wm = (wid & 3) * 32, wn = (wid >> 2) * 64;
    int g = lane >> 2, tg = lane & 3;

    float acc[2][8][4] = {};

    for (int kt = 0; kt < 16; kt++) {
        int k0 = kt * 48, ci0 = kt * 16;
        __syncthreads();
        #pragma unroll
        for (int it = 0; it < 6; it++) {
            int idx = tid + it * 256;
            int row = idx / 12, seg = (idx % 12) * 4;
            *(float4*)&sA[row][seg] =
                *(const float4*)&w[(size_t)(m0 + row) * 768 + k0 + seg];
        }
        for (int idx = tid; idx < 16 * 132; idx += 256) {
            int c = idx / 132, p = idx % 132;
            if (p < 130) {
                int l = l0 - 1 + p;
                float v = 0.f;
                if (l >= 0 && l < L_) {
                    float2 f = st[b * C_ + ci0 + c];
                    float x = in[((size_t)(b * C_ + ci0 + c)) * L_ + l];
                    float y = fmaf(x, f.x, f.y);
                    v = f2tf_f(y / (1.f + expf(-y)));
                }
                #pragma unroll
                for (int t = 0; t < 3; t++) {
                    int j = p - t;
                    if (j >= 0 && j < 128) sB[j][3 * c + t] = v;
                }
            }
        }
        __syncthreads();

        #pragma unroll
        for (int ks = 0; ks < 6; ks++) {
            int kb = ks * 8 + tg;
            u32 afr[2][4], bfr[8][2];
            #pragma unroll
            for (int mt = 0; mt < 2; mt++) {
                int r = wm + mt * 16 + g;
                afr[mt][0] = __float_as_uint(sA[r][kb]);
                afr[mt][1] = __float_as_uint(sA[r + 8][kb]);
                afr[mt][2] = __float_as_uint(sA[r][kb + 4]);
                afr[mt][3] = __float_as_uint(sA[r + 8][kb + 4]);
            }
            #pragma unroll
            for (int nt = 0; nt < 8; nt++) {
                int c = wn + nt * 8 + g;
                bfr[nt][0] = __float_as_uint(sB[c][kb]);
                bfr[nt][1] = __float_as_uint(sB[c][kb + 4]);
            }
            #pragma unroll
            for (int mt = 0; mt < 2; mt++)
                #pragma unroll
                for (int nt = 0; nt < 8; nt++)
                    MMA_TF32(acc[mt][nt], afr[mt], bfr[nt]);
        }
    }

    #pragma unroll
    for (int mt = 0; mt < 2; mt++) {
        #pragma unroll
        for (int half = 0; half < 2; half++) {
            int m = m0 + wm + mt * 16 + g + half * 8;
            float base = bias[m];
            if (ADDV) base += addv[b * C_ + m];
            #pragma unroll
            for (int nt = 0; nt < 8; nt++) {
                int n = l0 + wn + nt * 8 + tg * 2;
                float v0 = acc[mt][nt][half * 2 + 0] + base;
                float v1 = acc[mt][nt][half * 2 + 1] + base;
                size_t off = ((size_t)(b * C_ + m)) * L_ + n;
                if (RES) {
                    float2 r2 = *(const float2*)&resid[off];
                    v0 += r2.x; v1 += r2.y;
                }
                *(float2*)&out[off] = make_float2(v0, v1);
            }
        }
    }
}

// ---------------------------------------------------------------------------
// Row softmax in-place, float4 vectorized, tf32-round on store.
// One block (256 thr) per (b,i) row.
// ---------------------------------------------------------------------------
__global__ __launch_bounds__(256) void softmax_kernel(float* __restrict__ w)
{
    __shared__ float red[8];
    __shared__ float red2[8];
    size_t row = blockIdx.x;
    float4* p4 = (float4*)(w + row * (size_t)L_);
    int tid = threadIdx.x;

    float4 a = p4[tid];
    float4 b = p4[tid + 256];
    float v[8] = { a.x, a.y, a.z, a.w, b.x, b.y, b.z, b.w };

    float mx = v[0];
    #pragma unroll
    for (int i = 1; i < 8; i++) mx = fmaxf(mx, v[i]);
    #pragma unroll
    for (int o = 16; o > 0; o >>= 1) mx = fmaxf(mx, __shfl_xor_sync(0xffffffffu, mx, o));
    if ((tid & 31) == 0) red[tid >> 5] = mx;
    __syncthreads();
    float m = red[0];
    #pragma unroll
    for (int i = 1; i < 8; i++) m = fmaxf(m, red[i]);

    float s = 0.f;
    #pragma unroll
    for (int i = 0; i < 8; i++) { v[i] = expf(v[i] - m); s += v[i]; }
    #pragma unroll
    for (int o = 16; o > 0; o >>= 1) s += __shfl_xor_sync(0xffffffffu, s, o);
    if ((tid & 31) == 0) red2[tid >> 5] = s;
    __syncthreads();
    float tot = 0.f;
    #pragma unroll
    for (int i = 0; i < 8; i++) tot += red2[i];
    float inv = 1.f / tot;

    float4 oa, ob;
    oa.x = f2tf_f(v[0] * inv); oa.y = f2tf_f(v[1] * inv);
    oa.z = f2tf_f(v[2] * inv); oa.w = f2tf_f(v[3] * inv);
    ob.x = f2tf_f(v[4] * inv); ob.y = f2tf_f(v[5] * inv);
    ob.z = f2tf_f(v[6] * inv); ob.w = f2tf_f(v[7] * inv);
    p4[tid]       = oa;
    p4[tid + 256] = ob;
}

// ---------------------------------------------------------------------------
// Host orchestration (graph-capturable: kernel launches only)
// ---------------------------------------------------------------------------
extern "C" void kernel_launch(void* const* d_in, const int* in_sizes, int n_in,
                              void* d_out, int out_size)
{
    (void)in_sizes; (void)n_in; (void)out_size;

    const float* x   = (const float*)d_in[0];
    const int*   t   = (const int*)  d_in[1];
    const float* z0  = (const float*)d_in[2];
    const float* zt  = (const float*)d_in[3];
    const float* tw1 = (const float*)d_in[4];
    const float* tb1 = (const float*)d_in[5];
    const float* tw2 = (const float*)d_in[6];
    const float* tb2 = (const float*)d_in[7];
    const float* tpw = (const float*)d_in[8];
    const float* tpb = (const float*)d_in[9];
    const float* zpw = (const float*)d_in[10];
    const float* zpb = (const float*)d_in[11];
    const float* n1g = (const float*)d_in[12];
    const float* n1b = (const float*)d_in[13];
    const float* n2g = (const float*)d_in[14];
    const float* n2b = (const float*)d_in[15];
    const float* ng  = (const float*)d_in[16];
    const float* nb  = (const float*)d_in[17];
    const float* c1w = (const float*)d_in[18];
    const float* c1b = (const float*)d_in[19];
    const float* c2w = (const float*)d_in[20];
    const float* c2b = (const float*)d_in[21];
    const float* qw  = (const float*)d_in[22];
    const float* qb  = (const float*)d_in[23];
    const float* kw  = (const float*)d_in[24];
    const float* kb  = (const float*)d_in[25];
    const float* vw  = (const float*)d_in[26];
    const float* vb  = (const float*)d_in[27];
    const float* pw  = (const float*)d_in[28];
    const float* pb  = (const float*)d_in[29];
    float* out = (float*)d_out;

    float *p_h, *p_x1, *p_hnT, *p_qk, *p_v, *p_h2T, *p_sc, *p_add, *p_wr;
    float2* p_st;
    cudaGetSymbolAddress((void**)&p_h,   g_h);
    cudaGetSymbolAddress((void**)&p_x1,  g_x1);
    cudaGetSymbolAddress((void**)&p_hnT, g_hnT);
    cudaGetSymbolAddress((void**)&p_qk,  g_qk);
    cudaGetSymbolAddress((void**)&p_v,   g_v);
    cudaGetSymbolAddress((void**)&p_h2T, g_h2T);
    cudaGetSymbolAddress((void**)&p_sc,  g_sc);
    cudaGetSymbolAddress((void**)&p_add, g_add);
    cudaGetSymbolAddress((void**)&p_wr,  g_wr);
    cudaGetSymbolAddress((void**)&p_st,  g_st);

    float* wr_qk  = p_wr;                                    // [512][256]
    float* wr_v   = p_wr + 512 * C_;                         // [256][256]
    float* wr_p   = wr_v + C_ * C_;                          // [256][256]
    float* wr_c1  = wr_p + C_ * C_;                          // [256][768]
    float* wr_c2  = wr_c1 + C_ * C_ * 3;                     // [256][768]
    float* b_qk   = wr_c2 + C_ * C_ * 3;                     // [512]

    // dynamic-smem attribute for conv (host-side, idempotent)
    cudaFuncSetAttribute(conv_tf32<true, false>,
                         cudaFuncAttributeMaxDynamicSharedMemorySize, CONV_SMEM);
    cudaFuncSetAttribute(conv_tf32<false, true>,
                         cudaFuncAttributeMaxDynamicSharedMemorySize, CONV_SMEM);

    const size_t sCL  = (size_t)C_ * L_;    // [B,C,L] / [B,L,C] batch stride
    const size_t sQK  = (size_t)L_ * 512;   // [B,L,512] batch stride
    const size_t sLL  = (size_t)L_ * L_;    // [B,L,L] batch stride

    dim3 gconv(L_ / 128, C_ / 128, B_);

    // weight prep + temb
    round_tf32_kernel<<<(C_ * C_ * 3 + 255) / 256, 256>>>(c1w, wr_c1, C_ * C_ * 3);
    round_tf32_kernel<<<(C_ * C_ * 3 + 255) / 256, 256>>>(c2w, wr_c2, C_ * C_ * 3);
    temb_kernel<<<B_, 512>>>(t, z0, zt, tw1, tb1, tw2, tb2, tpw, tpb, zpw, zpb);

    // stage 1: stats(x, n1) -> conv1 with fused norm+silu loader, + add
    stats_kernel<<<B_ * C_, 256>>>(x, n1g, n1b, p_st);
    round_concat_qk<<<(512 * C_ + 255) / 256, 256>>>(qw, kw, qb, kb, wr_qk, b_qk);
    conv_tf32<true, false><<<gconv, 256, CONV_SMEM>>>(x, p_st, wr_c1, c1b,
                                                      p_add, nullptr, p_h);

    round_tf32_kernel<<<(C_ * C_ + 255) / 256, 256>>>(vw, wr_v, C_ * C_);
    round_tf32_kernel<<<(C_ * C_ + 255) / 256, 256>>>(pw, wr_p, C_ * C_);

    // stage 2: stats(h, n2) -> conv2 fused, residual x
    stats_kernel<<<B_ * C_, 256>>>(p_h, n2g, n2b, p_st);
    conv_tf32<false, true><<<gconv, 256, CONV_SMEM>>>(p_h, p_st, wr_c2, c2b,
                                                      nullptr, x, p_x1);

    // stage 3: stats(x1, n) -> fused norm+transpose -> hnT [B][L][C] tf32
    stats_kernel<<<B_ * C_, 256>>>(p_x1, ng, nb, p_st);
    dim3 gtr(L_ / 32, C_ / 32, B_);
    transpose_norm<<<gtr, 256>>>(p_x1, p_st, p_hnT);

    // qk [L][512] = hnT @ [qw;kw]^T + b(per-n)    M=L, N=512, K=256
    dim3 gqk(512 / 128, L_ / 128, B_);
    gemm_tf32<2, false, true><<<gqk, 256>>>(
        p_hnT, wr_qk, b_qk, nullptr, p_qk,
        C_, C_, C_, 512, 1.f, sCL, 0, sQK);
    // v [C][L] = vw @ hn + b(per-m)               M=C, N=L, K=256
    dim3 gv(L_ / 128, C_ / 128, B_);
    gemm_tf32<1, false, true><<<gv, 256>>>(
        wr_v, p_hnT, vb, nullptr, p_v,
        C_, C_, C_, L_, 1.f, 0, sCL, sCL);

    // scores[i][j] = (1/16) q[i]·k[j]             M=N=L, K=256 (ld 512)
    dim3 gsc(L_ / 128, L_ / 128, B_);
    gemm_tf32<0, false, false><<<gsc, 256>>>(
        p_qk, p_qk + 256, nullptr, nullptr, p_sc,
        C_, 512, 512, L_, 0.0625f, sQK, sQK, sLL);

    // softmax over j (in place, tf32 out)
    softmax_kernel<<<B_ * L_, 256>>>(p_sc);

    // h2T[i][c] = sum_j sc[i][j] v[c][j]          M=L, N=C, K=L
    dim3 gh2(C_ / 128, L_ / 128, B_);
    gemm_tf32<0, false, true><<<gh2, 256>>>(
        p_sc, p_v, nullptr, nullptr, p_h2T,
        L_, L_, L_, C_, 1.f, sLL, sCL, sCL);

    // out[c][l] = pw @ h2 + pb + x1               M=C, N=L, K=256
    dim3 gpr(L_ / 128, C_ / 128, B_);
    gemm_tf32<1, true, false><<<gpr, 256>>>(
        wr_p, p_h2T, pb, p_x1, out,
        C_, C_, C_, L_, 1.f, 0, sCL, sCL);
}

// round 9
// speedup vs baseline: 1.1278x; 1.1278x over previous
#include <cuda_runtime.h>
#include <math.h>
#include <stdint.h>

typedef unsigned int u32;

// ---------------------------------------------------------------------------
// Problem constants
// ---------------------------------------------------------------------------
constexpr int B_    = 16;
constexpr int C_    = 256;
constexpr int L_    = 2048;
constexpr int ZD_   = 128;
constexpr int TEMB_ = 512;
constexpr size_t BCL = (size_t)B_ * C_ * L_;
constexpr size_t BLL = (size_t)B_ * L_ * L_;

// ---------------------------------------------------------------------------
// Scratch (device globals; allocation-free per harness rules)
// ---------------------------------------------------------------------------
__device__ float  g_t1 [BCL];                    // silu(norm(.)) staging (tf32)
__device__ float  g_h  [BCL];                    // conv1 output
__device__ float  g_x1 [BCL];                    // x + conv2(...)
__device__ float  g_hnT[BCL];                    // norm(x1)^T [B][L][C] (tf32)
__device__ float  g_qk [(size_t)B_ * L_ * 512];  // q|k fused: [B][L][512] (tf32)
__device__ float  g_v  [BCL];                    // v   [B][C][L] (tf32)
__device__ float  g_h2T[BCL];                    // attn out [B][L][C] (tf32)
__device__ float  g_sc [BLL];                    // scores fp32 / softmax out (tf32)
__device__ float  g_add[B_ * C_];                // temb/z projection vector
__device__ float2 g_st [B_ * C_];                // per-row norm fold (fA, fB)
// tf32-pre-rounded weights: qk(512x256) | vw | pw | c1w | c2w ; then qk bias
__device__ float g_wr[512 * C_ + 2 * C_ * C_ + 2 * C_ * C_ * 3 + 512];

static __device__ __forceinline__ float silu_f(float x) {
    return x / (1.f + expf(-x));
}

static __device__ __forceinline__ float f2tf_f(float x) {
    u32 r;
    asm("cvt.rna.tf32.f32 %0, %1;" : "=r"(r) : "f"(x));
    return __uint_as_float(r);
}

#define MMA_TF32(d, a, b)                                                     \
    asm volatile("mma.sync.aligned.m16n8k8.row.col.f32.tf32.tf32.f32 "       \
                 "{%0,%1,%2,%3},{%4,%5,%6,%7},{%8,%9},{%0,%1,%2,%3};"         \
                 : "+f"(d[0]), "+f"(d[1]), "+f"(d[2]), "+f"(d[3])             \
                 : "r"(a[0]), "r"(a[1]), "r"(a[2]), "r"(a[3]),                \
                   "r"(b[0]), "r"(b[1]))

#define CP_ASYNC16(dst_u32, src_ptr)                                          \
    asm volatile("cp.async.cg.shared.global [%0], [%1], 16;"                  \
                 :: "r"(dst_u32), "l"(src_ptr))
#define CP_COMMIT()  asm volatile("cp.async.commit_group;")
#define CP_WAIT0()   asm volatile("cp.async.wait_group 0;")
#define CP_WAIT1()   asm volatile("cp.async.wait_group 1;")

static __device__ __forceinline__ u32 smem_u32(const void* p) {
    return (u32)__cvta_generic_to_shared(p);
}

// ---------------------------------------------------------------------------
// Weight prep kernels (tiny, run once per launch)
// ---------------------------------------------------------------------------
__global__ void round_tf32_kernel(const float* __restrict__ in,
                                  float* __restrict__ out, int n)
{
    int i = blockIdx.x * 256 + threadIdx.x;
    if (i < n) out[i] = f2tf_f(in[i]);
}

// concat qw|kw rows (512x256) + qb|kb (512), tf32-round weights
__global__ void round_concat_qk(const float* __restrict__ qw,
                                const float* __restrict__ kw,
                                const float* __restrict__ qb,
                                const float* __restrict__ kb,
                                float* __restrict__ wdst,
                                float* __restrict__ bdst)
{
    int i = blockIdx.x * 256 + threadIdx.x;
    int total = 512 * C_;
    if (i < total) {
        int n = i >> 8;   // /256
        wdst[i] = f2tf_f(n < C_ ? qw[i] : kw[i - C_ * C_]);
    }
    if (i < 512) bdst[i] = (i < C_) ? qb[i] : kb[i - C_];
}

// ---------------------------------------------------------------------------
// Kernel: timestep embedding MLP + fused add-vector
// ---------------------------------------------------------------------------
__global__ void temb_kernel(const int* __restrict__ t,
                            const float* __restrict__ z0,
                            const float* __restrict__ zt,
                            const float* __restrict__ tw1, const float* __restrict__ tb1,
                            const float* __restrict__ tw2, const float* __restrict__ tb2,
                            const float* __restrict__ tpw, const float* __restrict__ tpb,
                            const float* __restrict__ zpw, const float* __restrict__ zpb)
{
    __shared__ float se[128];
    __shared__ float s1[512];
    __shared__ float s2[512];
    __shared__ float sz[256];

    int b = blockIdx.x, tid = threadIdx.x;

    if (tid < 64) {
        float f = expf((float)tid * (-logf(10000.f) / 63.f));
        float a = (float)t[b] * f;
        se[tid]      = sinf(a);
        se[64 + tid] = cosf(a);
    }
    if (tid < 128) {
        sz[tid]       = silu_f(z0[b * ZD_ + tid]);
        sz[128 + tid] = silu_f(zt[b * ZD_ + tid]);
    }
    __syncthreads();

    {
        float acc = tb1[tid];
        #pragma unroll 8
        for (int i = 0; i < 128; i++) acc += se[i] * tw1[i * TEMB_ + tid];
        s1[tid] = silu_f(acc);
    }
    __syncthreads();
    {
        float acc = tb2[tid];
        #pragma unroll 8
        for (int k = 0; k < 512; k++) acc += s1[k] * tw2[k * TEMB_ + tid];
        s2[tid] = silu_f(acc);
    }
    __syncthreads();

    if (tid < C_) {
        float acc = tpb[tid] + 2.f * zpb[tid];
        #pragma unroll 8
        for (int j = 0; j < 512; j++) acc += s2[j] * tpw[j * C_ + tid];
        #pragma unroll 8
        for (int i = 0; i < 128; i++) acc += (sz[i] + sz[128 + i]) * zpw[i * C_ + tid];
        g_add[b * C_ + tid] = acc;
    }
}

// ---------------------------------------------------------------------------
// Kernel: per-(b,c) channel norm over L, fused silu + tf32 round (conv input).
// ---------------------------------------------------------------------------
__global__ __launch_bounds__(256) void norm_kernel(const float* __restrict__ in,
                                                   float* __restrict__ out,
                                                   const float* __restrict__ gam,
                                                   const float* __restrict__ bet)
{
    __shared__ float red[64];
    int row = blockIdx.x, tid = threadIdx.x;
    const float4* p4 = (const float4*)(in + (size_t)row * L_);

    float4 a = p4[tid];
    float4 b = p4[tid + 256];
    float v[8] = { a.x, a.y, a.z, a.w, b.x, b.y, b.z, b.w };
    float s = 0.f, sq = 0.f;
    #pragma unroll
    for (int i = 0; i < 8; i++) { s += v[i]; sq += v[i] * v[i]; }

    #pragma unroll
    for (int o = 16; o > 0; o >>= 1) {
        s  += __shfl_down_sync(0xffffffffu, s,  o);
        sq += __shfl_down_sync(0xffffffffu, sq, o);
    }
    if ((tid & 31) == 0) { red[tid >> 5] = s; red[8 + (tid >> 5)] = sq; }
    __syncthreads();
    if (tid < 32) {
        float aa = (tid < 8) ? red[tid]     : 0.f;
        float b2 = (tid < 8) ? red[8 + tid] : 0.f;
        #pragma unroll
        for (int o = 4; o > 0; o >>= 1) {
            aa += __shfl_down_sync(0xffffffffu, aa, o);
            b2 += __shfl_down_sync(0xffffffffu, b2, o);
        }
        if (tid == 0) { red[32] = aa; red[33] = b2; }
    }
    __syncthreads();

    float mean = red[32] * (1.f / L_);
    float var  = red[33] * (1.f / L_) - mean * mean;
    float rstd = rsqrtf(var + 1e-6f);
    int c = row & (C_ - 1);
    float gm = gam[c], bt = bet[c];

    float4* q4 = (float4*)(out + (size_t)row * L_);
    float o8[8];
    #pragma unroll
    for (int i = 0; i < 8; i++) {
        float y = (v[i] - mean) * rstd * gm + bt;
        o8[i] = f2tf_f(y / (1.f + expf(-y)));
    }
    q4[tid]       = make_float4(o8[0], o8[1], o8[2], o8[3]);
    q4[tid + 256] = make_float4(o8[4], o8[5], o8[6], o8[7]);
}

// ---------------------------------------------------------------------------
// Kernel: per-(b,c) norm statistics -> fold factors (fA, fB) for stage 3.
// ---------------------------------------------------------------------------
__global__ __launch_bounds__(256) void stats_kernel(const float* __restrict__ in,
                                                    const float* __restrict__ gam,
                                                    const float* __restrict__ bet,
                                                    float2* __restrict__ st)
{
    __shared__ float red[64];
    int row = blockIdx.x, tid = threadIdx.x;
    const float4* p4 = (const float4*)(in + (size_t)row * L_);

    float4 a = p4[tid];
    float4 b = p4[tid + 256];
    float s  = a.x + a.y + a.z + a.w + b.x + b.y + b.z + b.w;
    float sq = a.x * a.x + a.y * a.y + a.z * a.z + a.w * a.w
             + b.x * b.x + b.y * b.y + b.z * b.z + b.w * b.w;

    #pragma unroll
    for (int o = 16; o > 0; o >>= 1) {
        s  += __shfl_down_sync(0xffffffffu, s,  o);
        sq += __shfl_down_sync(0xffffffffu, sq, o);
    }
    if ((tid & 31) == 0) { red[tid >> 5] = s; red[8 + (tid >> 5)] = sq; }
    __syncthreads();
    if (tid == 0) {
        float S = 0.f, SQ = 0.f;
        #pragma unroll
        for (int i = 0; i < 8; i++) { S += red[i]; SQ += red[8 + i]; }
        float mean = S * (1.f / L_);
        float var  = SQ * (1.f / L_) - mean * mean;
        float rstd = rsqrtf(var + 1e-6f);
        int c = row & (C_ - 1);
        float fA = rstd * gam[c];
        st[row] = make_float2(fA, bet[c] - mean * fA);
    }
}

// ---------------------------------------------------------------------------
// Kernel: fused norm + 32x32 transpose, [B][C][L] -> [B][L][C], tf32 out.
// ---------------------------------------------------------------------------
__global__ __launch_bounds__(256) void transpose_norm(const float* __restrict__ in,
                                                      const float2* __restrict__ st,
                                                      float* __restrict__ out)
{
    __shared__ float tile[32][33];
    int b = blockIdx.z;
    int l0 = blockIdx.x * 32, c0 = blockIdx.y * 32;
    int tx = threadIdx.x & 31, ty = threadIdx.x >> 5;
    #pragma unroll
    for (int i = 0; i < 4; i++) {
        int c = c0 + ty + i * 8;
        float2 f = st[b * C_ + c];
        float x = in[((size_t)(b * C_ + c)) * L_ + l0 + tx];
        tile[ty + i * 8][tx] = f2tf_f(fmaf(x, f.x, f.y));
    }
    __syncthreads();
    #pragma unroll
    for (int i = 0; i < 4; i++) {
        int l = l0 + ty + i * 8;
        out[((size_t)b * L_ + l) * C_ + c0 + tx] = tile[tx][ty + i * 8];
    }
}

// ---------------------------------------------------------------------------
// tf32 tensor-core GEMM — cp.async 2-stage pipeline, k-tile 32,
// FORCED 2 CTAs/SM via __launch_bounds__(256, 2).
//   C[m][n] = alpha * sum_k A[m][k] * B[n][k]  (generalized lda/ldb/ldc)
// Operands MUST be tf32-representable (pre-rounded).
// BIAS_MODE: 0 none, 1 per-m, 2 per-n. RES: fp32 residual. OTF32: round out.
// ---------------------------------------------------------------------------
constexpr int GEMM_SMEM = 2 * 2 * 128 * 36 * 4;   // 73728 B; x2 CTAs = 147 KB

template <int BIAS_MODE, bool RES, bool OTF32>
__global__ __launch_bounds__(256, 2) void gemm_tf32(
    const float* __restrict__ A, const float* __restrict__ Bm,
    const float* __restrict__ bias, const float* __restrict__ res,
    float* __restrict__ Cout, int K, int lda, int ldb, int ldc,
    float alpha, size_t strideA, size_t strideB, size_t strideC)
{
    extern __shared__ float smem[];
    float (*sA)[128][36] = (float(*)[128][36])smem;                    // [stage]
    float (*sB)[128][36] = (float(*)[128][36])(smem + 2 * 128 * 36);

    int bz = blockIdx.z;
    A  += strideA * bz;
    Bm += strideB * bz;

    int m0 = blockIdx.y * 128, n0 = blockIdx.x * 128;
    int tid = threadIdx.x, lane = tid & 31, w = tid >> 5;
    int wm = (w & 3) * 32, wn = (w >> 2) * 64;
    int g = lane >> 2, tg = lane & 3;

    // per-thread copy coords: 4 iterations x (A row + B row), 16B each
    int crow[4], cseg[4];
    #pragma unroll
    for (int it = 0; it < 4; it++) {
        int idx = tid + it * 256;
        crow[it] = idx >> 3;
        cseg[it] = (idx & 7) * 4;
    }

    float acc[2][8][4] = {};
    int KT = K / 32;

    // prologue: stage 0
    #pragma unroll
    for (int it = 0; it < 4; it++) {
        CP_ASYNC16(smem_u32(&sA[0][crow[it]][cseg[it]]),
                   &A[(size_t)(m0 + crow[it]) * lda + cseg[it]]);
        CP_ASYNC16(smem_u32(&sB[0][crow[it]][cseg[it]]),
                   &Bm[(size_t)(n0 + crow[it]) * ldb + cseg[it]]);
    }
    CP_COMMIT();

    for (int kt = 0; kt < KT; kt++) {
        int st = kt & 1;
        if (kt + 1 < KT) {
            int k1 = (kt + 1) * 32, s1 = (kt + 1) & 1;
            #pragma unroll
            for (int it = 0; it < 4; it++) {
                CP_ASYNC16(smem_u32(&sA[s1][crow[it]][cseg[it]]),
                           &A[(size_t)(m0 + crow[it]) * lda + k1 + cseg[it]]);
                CP_ASYNC16(smem_u32(&sB[s1][crow[it]][cseg[it]]),
                           &Bm[(size_t)(n0 + crow[it]) * ldb + k1 + cseg[it]]);
            }
            CP_COMMIT();
            CP_WAIT1();
        } else {
            CP_WAIT0();
        }
        __syncthreads();

        #pragma unroll
        for (int ks = 0; ks < 4; ks++) {
            int kb = ks * 8 + tg;
            u32 afr[2][4], bfr[8][2];
            #pragma unroll
            for (int mt = 0; mt < 2; mt++) {
                int r = wm + mt * 16 + g;
                afr[mt][0] = __float_as_uint(sA[st][r][kb]);
                afr[mt][1] = __float_as_uint(sA[st][r + 8][kb]);
                afr[mt][2] = __float_as_uint(sA[st][r][kb + 4]);
                afr[mt][3] = __float_as_uint(sA[st][r + 8][kb + 4]);
            }
            #pragma unroll
            for (int nt = 0; nt < 8; nt++) {
                int c = wn + nt * 8 + g;
                bfr[nt][0] = __float_as_uint(sB[st][c][kb]);
                bfr[nt][1] = __float_as_uint(sB[st][c][kb + 4]);
            }
            #pragma unroll
            for (int mt = 0; mt < 2; mt++)
                #pragma unroll
                for (int nt = 0; nt < 8; nt++)
                    MMA_TF32(acc[mt][nt], afr[mt], bfr[nt]);
        }
        __syncthreads();
    }

    // epilogue
    #pragma unroll
    for (int mt = 0; mt < 2; mt++) {
        #pragma unroll
        for (int half = 0; half < 2; half++) {
            int m = m0 + wm + mt * 16 + g + half * 8;
            float bm = (BIAS_MODE == 1) ? bias[m] : 0.f;
            #pragma unroll
            for (int nt = 0; nt < 8; nt++) {
                int n = n0 + wn + nt * 8 + tg * 2;
                float v0 = acc[mt][nt][half * 2 + 0] * alpha;
                float v1 = acc[mt][nt][half * 2 + 1] * alpha;
                if (BIAS_MODE == 1) { v0 += bm; v1 += bm; }
                if (BIAS_MODE == 2) { v0 += bias[n]; v1 += bias[n + 1]; }
                size_t off = strideC * bz + (size_t)m * ldc + n;
                if (RES) {
                    float2 r2 = *(const float2*)&res[off];
                    v0 += r2.x; v1 += r2.y;
                }
                if (OTF32) { v0 = f2tf_f(v0); v1 = f2tf_f(v1); }
                *(float2*)&Cout[off] = make_float2(v0, v1);
            }
        }
    }
}

// ---------------------------------------------------------------------------
// tf32 tensor-core 3-tap conv (implicit GEMM) — R7 form, 2 CTAs/SM forced,
// plain loader (input = pre-rounded silu(norm(.)) from norm_kernel).
// M=C (co), N=L(128-tile), K=768 in 16 chunks of 48 (16 ci x 3 taps).
// ---------------------------------------------------------------------------
constexpr int CONV_SMEM = 2 * 128 * 52 * 4;   // 53248 B (dynamic, 2 CTAs/SM)

template <bool ADDV, bool RES>
__global__ __launch_bounds__(256, 2) void conv_tf32(
    const float* __restrict__ in,   // [B][C][L] (tf32 values)
    const float* __restrict__ w,    // [C][768]  (tf32 values)
    const float* __restrict__ bias,
    const float* __restrict__ addv,
    const float* __restrict__ resid,
    float* __restrict__ out)
{
    extern __shared__ float smemc[];
    float (*sA)[52] = (float(*)[52])smemc;              // weights [co][48]
    float (*sB)[52] = (float(*)[52])(smemc + 128 * 52); // patch   [l][48]

    int b  = blockIdx.z;
    int m0 = blockIdx.y * 128;
    int l0 = blockIdx.x * 128;
    int tid = threadIdx.x, lane = tid & 31, wid = tid >> 5;
    int wm = (wid & 3) * 32, wn = (wid >> 2) * 64;
    int g = lane >> 2, tg = lane & 3;

    float acc[2][8][4] = {};

    for (int kt = 0; kt < 16; kt++) {
        int k0 = kt * 48, ci0 = kt * 16;
        __syncthreads();
        #pragma unroll
        for (int it = 0; it < 6; it++) {
            int idx = tid + it * 256;
            int row = idx / 12, seg = (idx % 12) * 4;
            *(float4*)&sA[row][seg] =
                *(const float4*)&w[(size_t)(m0 + row) * 768 + k0 + seg];
        }
        for (int idx = tid; idx < 16 * 132; idx += 256) {
            int c = idx / 132, p = idx % 132;
            if (p < 130) {
                int l = l0 - 1 + p;
                float v = 0.f;
                if (l >= 0 && l < L_)
                    v = in[((size_t)(b * C_ + ci0 + c)) * L_ + l];
                #pragma unroll
                for (int t = 0; t < 3; t++) {
                    int j = p - t;
                    if (j >= 0 && j < 128) sB[j][3 * c + t] = v;
                }
            }
        }
        __syncthreads();

        #pragma unroll
        for (int ks = 0; ks < 6; ks++) {
            int kb = ks * 8 + tg;
            u32 afr[2][4], bfr[8][2];
            #pragma unroll
            for (int mt = 0; mt < 2; mt++) {
                int r = wm + mt * 16 + g;
                afr[mt][0] = __float_as_uint(sA[r][kb]);
                afr[mt][1] = __float_as_uint(sA[r + 8][kb]);
                afr[mt][2] = __float_as_uint(sA[r][kb + 4]);
                afr[mt][3] = __float_as_uint(sA[r + 8][kb + 4]);
            }
            #pragma unroll
            for (int nt = 0; nt < 8; nt++) {
                int c = wn + nt * 8 + g;
                bfr[nt][0] = __float_as_uint(sB[c][kb]);
                bfr[nt][1] = __float_as_uint(sB[c][kb + 4]);
            }
            #pragma unroll
            for (int mt = 0; mt < 2; mt++)
                #pragma unroll
                for (int nt = 0; nt < 8; nt++)
                    MMA_TF32(acc[mt][nt], afr[mt], bfr[nt]);
        }
    }

    #pragma unroll
    for (int mt = 0; mt < 2; mt++) {
        #pragma unroll
        for (int half = 0; half < 2; half++) {
            int m = m0 + wm + mt * 16 + g + half * 8;
            float base = bias[m];
            if (ADDV) base += addv[b * C_ + m];
            #pragma unroll
            for (int nt = 0; nt < 8; nt++) {
                int n = l0 + wn + nt * 8 + tg * 2;
                float v0 = acc[mt][nt][half * 2 + 0] + base;
                float v1 = acc[mt][nt][half * 2 + 1] + base;
                size_t off = ((size_t)(b * C_ + m)) * L_ + n;
                if (RES) {
                    float2 r2 = *(const float2*)&resid[off];
                    v0 += r2.x; v1 += r2.y;
                }
                *(float2*)&out[off] = make_float2(v0, v1);
            }
        }
    }
}

// ---------------------------------------------------------------------------
// Row softmax in-place, float4 vectorized, tf32-round on store.
// ---------------------------------------------------------------------------
__global__ __launch_bounds__(256) void softmax_kernel(float* __restrict__ w)
{
    __shared__ float red[8];
    __shared__ float red2[8];
    size_t row = blockIdx.x;
    float4* p4 = (float4*)(w + row * (size_t)L_);
    int tid = threadIdx.x;

    float4 a = p4[tid];
    float4 b = p4[tid + 256];
    float v[8] = { a.x, a.y, a.z, a.w, b.x, b.y, b.z, b.w };

    float mx = v[0];
    #pragma unroll
    for (int i = 1; i < 8; i++) mx = fmaxf(mx, v[i]);
    #pragma unroll
    for (int o = 16; o > 0; o >>= 1) mx = fmaxf(mx, __shfl_xor_sync(0xffffffffu, mx, o));
    if ((tid & 31) == 0) red[tid >> 5] = mx;
    __syncthreads();
    float m = red[0];
    #pragma unroll
    for (int i = 1; i < 8; i++) m = fmaxf(m, red[i]);

    float s = 0.f;
    #pragma unroll
    for (int i = 0; i < 8; i++) { v[i] = expf(v[i] - m); s += v[i]; }
    #pragma unroll
    for (int o = 16; o > 0; o >>= 1) s += __shfl_xor_sync(0xffffffffu, s, o);
    if ((tid & 31) == 0) red2[tid >> 5] = s;
    __syncthreads();
    float tot = 0.f;
    #pragma unroll
    for (int i = 0; i < 8; i++) tot += red2[i];
    float inv = 1.f / tot;

    float4 oa, ob;
    oa.x = f2tf_f(v[0] * inv); oa.y = f2tf_f(v[1] * inv);
    oa.z = f2tf_f(v[2] * inv); oa.w = f2tf_f(v[3] * inv);
    ob.x = f2tf_f(v[4] * inv); ob.y = f2tf_f(v[5] * inv);
    ob.z = f2tf_f(v[6] * inv); ob.w = f2tf_f(v[7] * inv);
    p4[tid]       = oa;
    p4[tid + 256] = ob;
}

// ---------------------------------------------------------------------------
// Host orchestration (graph-capturable: kernel launches only)
// ---------------------------------------------------------------------------
extern "C" void kernel_launch(void* const* d_in, const int* in_sizes, int n_in,
                              void* d_out, int out_size)
{
    (void)in_sizes; (void)n_in; (void)out_size;

    const float* x   = (const float*)d_in[0];
    const int*   t   = (const int*)  d_in[1];
    const float* z0  = (const float*)d_in[2];
    const float* zt  = (const float*)d_in[3];
    const float* tw1 = (const float*)d_in[4];
    const float* tb1 = (const float*)d_in[5];
    const float* tw2 = (const float*)d_in[6];
    const float* tb2 = (const float*)d_in[7];
    const float* tpw = (const float*)d_in[8];
    const float* tpb = (const float*)d_in[9];
    const float* zpw = (const float*)d_in[10];
    const float* zpb = (const float*)d_in[11];
    const float* n1g = (const float*)d_in[12];
    const float* n1b = (const float*)d_in[13];
    const float* n2g = (const float*)d_in[14];
    const float* n2b = (const float*)d_in[15];
    const float* ng  = (const float*)d_in[16];
    const float* nb  = (const float*)d_in[17];
    const float* c1w = (const float*)d_in[18];
    const float* c1b = (const float*)d_in[19];
    const float* c2w = (const float*)d_in[20];
    const float* c2b = (const float*)d_in[21];
    const float* qw  = (const float*)d_in[22];
    const float* qb  = (const float*)d_in[23];
    const float* kw  = (const float*)d_in[24];
    const float* kb  = (const float*)d_in[25];
    const float* vw  = (const float*)d_in[26];
    const float* vb  = (const float*)d_in[27];
    const float* pw  = (const float*)d_in[28];
    const float* pb  = (const float*)d_in[29];
    float* out = (float*)d_out;

    float *p_t1, *p_h, *p_x1, *p_hnT, *p_qk, *p_v, *p_h2T, *p_sc, *p_add, *p_wr;
    float2* p_st;
    cudaGetSymbolAddress((void**)&p_t1,  g_t1);
    cudaGetSymbolAddress((void**)&p_h,   g_h);
    cudaGetSymbolAddress((void**)&p_x1,  g_x1);
    cudaGetSymbolAddress((void**)&p_hnT, g_hnT);
    cudaGetSymbolAddress((void**)&p_qk,  g_qk);
    cudaGetSymbolAddress((void**)&p_v,   g_v);
    cudaGetSymbolAddress((void**)&p_h2T, g_h2T);
    cudaGetSymbolAddress((void**)&p_sc,  g_sc);
    cudaGetSymbolAddress((void**)&p_add, g_add);
    cudaGetSymbolAddress((void**)&p_wr,  g_wr);
    cudaGetSymbolAddress((void**)&p_st,  g_st);

    float* wr_qk  = p_wr;                                    // [512][256]
    float* wr_v   = p_wr + 512 * C_;                         // [256][256]
    float* wr_p   = wr_v + C_ * C_;                          // [256][256]
    float* wr_c1  = wr_p + C_ * C_;                          // [256][768]
    float* wr_c2  = wr_c1 + C_ * C_ * 3;                     // [256][768]
    float* b_qk   = wr_c2 + C_ * C_ * 3;                     // [512]

    // dynamic-smem attributes (host-side, idempotent)
    cudaFuncSetAttribute(gemm_tf32<2, false, true>,
                         cudaFuncAttributeMaxDynamicSharedMemorySize, GEMM_SMEM);
    cudaFuncSetAttribute(gemm_tf32<1, false, true>,
                         cudaFuncAttributeMaxDynamicSharedMemorySize, GEMM_SMEM);
    cudaFuncSetAttribute(gemm_tf32<0, false, false>,
                         cudaFuncAttributeMaxDynamicSharedMemorySize, GEMM_SMEM);
    cudaFuncSetAttribute(gemm_tf32<0, false, true>,
                         cudaFuncAttributeMaxDynamicSharedMemorySize, GEMM_SMEM);
    cudaFuncSetAttribute(gemm_tf32<1, true, false>,
                         cudaFuncAttributeMaxDynamicSharedMemorySize, GEMM_SMEM);
    cudaFuncSetAttribute(conv_tf32<true, false>,
                         cudaFuncAttributeMaxDynamicSharedMemorySize, CONV_SMEM);
    cudaFuncSetAttribute(conv_tf32<false, true>,
                         cudaFuncAttributeMaxDynamicSharedMemorySize, CONV_SMEM);

    const size_t sCL  = (size_t)C_ * L_;    // [B,C,L] / [B,L,C] batch stride
    const size_t sQK  = (size_t)L_ * 512;   // [B,L,512] batch stride
    const size_t sLL  = (size_t)L_ * L_;    // [B,L,L] batch stride

    dim3 gconv(L_ / 128, C_ / 128, B_);

    // weight prep + temb
    round_tf32_kernel<<<(C_ * C_ * 3 + 255) / 256, 256>>>(c1w, wr_c1, C_ * C_ * 3);
    round_tf32_kernel<<<(C_ * C_ * 3 + 255) / 256, 256>>>(c2w, wr_c2, C_ * C_ * 3);
    temb_kernel<<<B_, 512>>>(t, z0, zt, tw1, tb1, tw2, tb2, tpw, tpb, zpw, zpb);
    round_concat_qk<<<(512 * C_ + 255) / 256, 256>>>(qw, kw, qb, kb, wr_qk, b_qk);
    round_tf32_kernel<<<(C_ * C_ + 255) / 256, 256>>>(vw, wr_v, C_ * C_);
    round_tf32_kernel<<<(C_ * C_ + 255) / 256, 256>>>(pw, wr_p, C_ * C_);

    // stage 1: t1 = tf32(silu(chan_norm(x, n1))); h = conv1(t1) + add
    norm_kernel<<<B_ * C_, 256>>>(x, p_t1, n1g, n1b);
    conv_tf32<true, false><<<gconv, 256, CONV_SMEM>>>(p_t1, wr_c1, c1b,
                                                      p_add, nullptr, p_h);

    // stage 2: t1 = tf32(silu(chan_norm(h, n2))); x1 = x + conv2(t1)
    norm_kernel<<<B_ * C_, 256>>>(p_h, p_t1, n2g, n2b);
    conv_tf32<false, true><<<gconv, 256, CONV_SMEM>>>(p_t1, wr_c2, c2b,
                                                      nullptr, x, p_x1);

    // stage 3: stats(x1, n) -> fused norm+transpose -> hnT [B][L][C] tf32
    stats_kernel<<<B_ * C_, 256>>>(p_x1, ng, nb, p_st);
    dim3 gtr(L_ / 32, C_ / 32, B_);
    transpose_norm<<<gtr, 256>>>(p_x1, p_st, p_hnT);

    // qk [L][512] = hnT @ [qw;kw]^T + b(per-n)    M=L, N=512, K=256
    dim3 gqk(512 / 128, L_ / 128, B_);
    gemm_tf32<2, false, true><<<gqk, 256, GEMM_SMEM>>>(
        p_hnT, wr_qk, b_qk, nullptr, p_qk,
        C_, C_, C_, 512, 1.f, sCL, 0, sQK);
    // v [C][L] = vw @ hn + b(per-m)               M=C, N=L, K=256
    dim3 gv(L_ / 128, C_ / 128, B_);
    gemm_tf32<1, false, true><<<gv, 256, GEMM_SMEM>>>(
        wr_v, p_hnT, vb, nullptr, p_v,
        C_, C_, C_, L_, 1.f, 0, sCL, sCL);

    // scores[i][j] = (1/16) q[i]·k[j]             M=N=L, K=256 (ld 512)
    dim3 gsc(L_ / 128, L_ / 128, B_);
    gemm_tf32<0, false, false><<<gsc, 256, GEMM_SMEM>>>(
        p_qk, p_qk + 256, nullptr, nullptr, p_sc,
        C_, 512, 512, L_, 0.0625f, sQK, sQK, sLL);

    // softmax over j (in place, tf32 out)
    softmax_kernel<<<B_ * L_, 256>>>(p_sc);

    // h2T[i][c] = sum_j sc[i][j] v[c][j]          M=L, N=C, K=L
    dim3 gh2(C_ / 128, L_ / 128, B_);
    gemm_tf32<0, false, true><<<gh2, 256, GEMM_SMEM>>>(
        p_sc, p_v, nullptr, nullptr, p_h2T,
        L_, L_, L_, C_, 1.f, sLL, sCL, sCL);

    // out[c][l] = pw @ h2 + pb + x1               M=C, N=L, K=256
    dim3 gpr(L_ / 128, C_ / 128, B_);
    gemm_tf32<1, true, false><<<gpr, 256, GEMM_SMEM>>>(
        wr_p, p_h2T, pb, p_x1, out,
        C_, C_, C_, L_, 1.f, 0, sCL, sCL);
}

// round 10
// speedup vs baseline: 1.2260x; 1.0871x over previous
#include <cuda_runtime.h>
#include <math.h>
#include <stdint.h>

typedef unsigned int u32;

// ---------------------------------------------------------------------------
// Problem constants
// ---------------------------------------------------------------------------
constexpr int B_    = 16;
constexpr int C_    = 256;
constexpr int L_    = 2048;
constexpr int ZD_   = 128;
constexpr int TEMB_ = 512;
constexpr size_t BCL = (size_t)B_ * C_ * L_;
constexpr size_t BLL = (size_t)B_ * L_ * L_;

// ---------------------------------------------------------------------------
// Scratch (device globals; allocation-free per harness rules)
// ---------------------------------------------------------------------------
__device__ float  g_t1 [BCL];                    // silu(norm(.)) staging (tf32)
__device__ float  g_h  [BCL];                    // conv1 output
__device__ float  g_x1 [BCL];                    // x + conv2(...)
__device__ float  g_hnT[BCL];                    // norm(x1)^T [B][L][C] (tf32)
__device__ float  g_qk [(size_t)B_ * L_ * 512];  // q|k fused: [B][L][512] (tf32)
__device__ float  g_v  [BCL];                    // v   [B][C][L] (tf32)
__device__ float  g_h2T[BCL];                    // attn out [B][L][C] (tf32)
__device__ float  g_sc [BLL];                    // scores fp32 / softmax out (tf32)
__device__ float  g_add[B_ * C_];                // temb/z projection vector
__device__ float2 g_st [B_ * C_];                // per-row norm fold (fA, fB)
// tf32-pre-rounded weights: qk(512x256) | vw | pw | c1w | c2w ; then qk bias
__device__ float g_wr[512 * C_ + 2 * C_ * C_ + 2 * C_ * C_ * 3 + 512];

static __device__ __forceinline__ float silu_f(float x) {
    return x / (1.f + expf(-x));
}

static __device__ __forceinline__ float f2tf_f(float x) {
    u32 r;
    asm("cvt.rna.tf32.f32 %0, %1;" : "=r"(r) : "f"(x));
    return __uint_as_float(r);
}

#define MMA_TF32(d, a, b)                                                     \
    asm volatile("mma.sync.aligned.m16n8k8.row.col.f32.tf32.tf32.f32 "       \
                 "{%0,%1,%2,%3},{%4,%5,%6,%7},{%8,%9},{%0,%1,%2,%3};"         \
                 : "+f"(d[0]), "+f"(d[1]), "+f"(d[2]), "+f"(d[3])             \
                 : "r"(a[0]), "r"(a[1]), "r"(a[2]), "r"(a[3]),                \
                   "r"(b[0]), "r"(b[1]))

#define CP_ASYNC16(dst_u32, src_ptr)                                          \
    asm volatile("cp.async.cg.shared.global [%0], [%1], 16;"                  \
                 :: "r"(dst_u32), "l"(src_ptr))
#define CP_COMMIT()  asm volatile("cp.async.commit_group;")
#define CP_WAIT0()   asm volatile("cp.async.wait_group 0;")
#define CP_WAIT1()   asm volatile("cp.async.wait_group 1;")

static __device__ __forceinline__ u32 smem_u32(const void* p) {
    return (u32)__cvta_generic_to_shared(p);
}

// ---------------------------------------------------------------------------
// Weight prep kernels (tiny, run once per launch)
// ---------------------------------------------------------------------------
__global__ void round_tf32_kernel(const float* __restrict__ in,
                                  float* __restrict__ out, int n)
{
    int i = blockIdx.x * 256 + threadIdx.x;
    if (i < n) out[i] = f2tf_f(in[i]);
}

// concat qw|kw rows (512x256) + qb|kb (512), tf32-round weights
__global__ void round_concat_qk(const float* __restrict__ qw,
                                const float* __restrict__ kw,
                                const float* __restrict__ qb,
                                const float* __restrict__ kb,
                                float* __restrict__ wdst,
                                float* __restrict__ bdst)
{
    int i = blockIdx.x * 256 + threadIdx.x;
    int total = 512 * C_;
    if (i < total) {
        int n = i >> 8;   // /256
        wdst[i] = f2tf_f(n < C_ ? qw[i] : kw[i - C_ * C_]);
    }
    if (i < 512) bdst[i] = (i < C_) ? qb[i] : kb[i - C_];
}

// ---------------------------------------------------------------------------
// Kernel: timestep embedding MLP + fused add-vector
// ---------------------------------------------------------------------------
__global__ void temb_kernel(const int* __restrict__ t,
                            const float* __restrict__ z0,
                            const float* __restrict__ zt,
                            const float* __restrict__ tw1, const float* __restrict__ tb1,
                            const float* __restrict__ tw2, const float* __restrict__ tb2,
                            const float* __restrict__ tpw, const float* __restrict__ tpb,
                            const float* __restrict__ zpw, const float* __restrict__ zpb)
{
    __shared__ float se[128];
    __shared__ float s1[512];
    __shared__ float s2[512];
    __shared__ float sz[256];

    int b = blockIdx.x, tid = threadIdx.x;

    if (tid < 64) {
        float f = expf((float)tid * (-logf(10000.f) / 63.f));
        float a = (float)t[b] * f;
        se[tid]      = sinf(a);
        se[64 + tid] = cosf(a);
    }
    if (tid < 128) {
        sz[tid]       = silu_f(z0[b * ZD_ + tid]);
        sz[128 + tid] = silu_f(zt[b * ZD_ + tid]);
    }
    __syncthreads();

    {
        float acc = tb1[tid];
        #pragma unroll 8
        for (int i = 0; i < 128; i++) acc += se[i] * tw1[i * TEMB_ + tid];
        s1[tid] = silu_f(acc);
    }
    __syncthreads();
    {
        float acc = tb2[tid];
        #pragma unroll 8
        for (int k = 0; k < 512; k++) acc += s1[k] * tw2[k * TEMB_ + tid];
        s2[tid] = silu_f(acc);
    }
    __syncthreads();

    if (tid < C_) {
        float acc = tpb[tid] + 2.f * zpb[tid];
        #pragma unroll 8
        for (int j = 0; j < 512; j++) acc += s2[j] * tpw[j * C_ + tid];
        #pragma unroll 8
        for (int i = 0; i < 128; i++) acc += (sz[i] + sz[128 + i]) * zpw[i * C_ + tid];
        g_add[b * C_ + tid] = acc;
    }
}

// ---------------------------------------------------------------------------
// Kernel: per-(b,c) channel norm over L, fused silu + tf32 round (conv input).
// ---------------------------------------------------------------------------
__global__ __launch_bounds__(256) void norm_kernel(const float* __restrict__ in,
                                                   float* __restrict__ out,
                                                   const float* __restrict__ gam,
                                                   const float* __restrict__ bet)
{
    __shared__ float red[64];
    int row = blockIdx.x, tid = threadIdx.x;
    const float4* p4 = (const float4*)(in + (size_t)row * L_);

    float4 a = p4[tid];
    float4 b = p4[tid + 256];
    float v[8] = { a.x, a.y, a.z, a.w, b.x, b.y, b.z, b.w };
    float s = 0.f, sq = 0.f;
    #pragma unroll
    for (int i = 0; i < 8; i++) { s += v[i]; sq += v[i] * v[i]; }

    #pragma unroll
    for (int o = 16; o > 0; o >>= 1) {
        s  += __shfl_down_sync(0xffffffffu, s,  o);
        sq += __shfl_down_sync(0xffffffffu, sq, o);
    }
    if ((tid & 31) == 0) { red[tid >> 5] = s; red[8 + (tid >> 5)] = sq; }
    __syncthreads();
    if (tid < 32) {
        float aa = (tid < 8) ? red[tid]     : 0.f;
        float b2 = (tid < 8) ? red[8 + tid] : 0.f;
        #pragma unroll
        for (int o = 4; o > 0; o >>= 1) {
            aa += __shfl_down_sync(0xffffffffu, aa, o);
            b2 += __shfl_down_sync(0xffffffffu, b2, o);
        }
        if (tid == 0) { red[32] = aa; red[33] = b2; }
    }
    __syncthreads();

    float mean = red[32] * (1.f / L_);
    float var  = red[33] * (1.f / L_) - mean * mean;
    float rstd = rsqrtf(var + 1e-6f);
    int c = row & (C_ - 1);
    float gm = gam[c], bt = bet[c];

    float4* q4 = (float4*)(out + (size_t)row * L_);
    float o8[8];
    #pragma unroll
    for (int i = 0; i < 8; i++) {
        float y = (v[i] - mean) * rstd * gm + bt;
        o8[i] = f2tf_f(y / (1.f + expf(-y)));
    }
    q4[tid]       = make_float4(o8[0], o8[1], o8[2], o8[3]);
    q4[tid + 256] = make_float4(o8[4], o8[5], o8[6], o8[7]);
}

// ---------------------------------------------------------------------------
// Kernel: per-(b,c) norm statistics -> fold factors (fA, fB) for stage 3.
// ---------------------------------------------------------------------------
__global__ __launch_bounds__(256) void stats_kernel(const float* __restrict__ in,
                                                    const float* __restrict__ gam,
                                                    const float* __restrict__ bet,
                                                    float2* __restrict__ st)
{
    __shared__ float red[64];
    int row = blockIdx.x, tid = threadIdx.x;
    const float4* p4 = (const float4*)(in + (size_t)row * L_);

    float4 a = p4[tid];
    float4 b = p4[tid + 256];
    float s  = a.x + a.y + a.z + a.w + b.x + b.y + b.z + b.w;
    float sq = a.x * a.x + a.y * a.y + a.z * a.z + a.w * a.w
             + b.x * b.x + b.y * b.y + b.z * b.z + b.w * b.w;

    #pragma unroll
    for (int o = 16; o > 0; o >>= 1) {
        s  += __shfl_down_sync(0xffffffffu, s,  o);
        sq += __shfl_down_sync(0xffffffffu, sq, o);
    }
    if ((tid & 31) == 0) { red[tid >> 5] = s; red[8 + (tid >> 5)] = sq; }
    __syncthreads();
    if (tid == 0) {
        float S = 0.f, SQ = 0.f;
        #pragma unroll
        for (int i = 0; i < 8; i++) { S += red[i]; SQ += red[8 + i]; }
        float mean = S * (1.f / L_);
        float var  = SQ * (1.f / L_) - mean * mean;
        float rstd = rsqrtf(var + 1e-6f);
        int c = row & (C_ - 1);
        float fA = rstd * gam[c];
        st[row] = make_float2(fA, bet[c] - mean * fA);
    }
}

// ---------------------------------------------------------------------------
// Kernel: fused norm + 32x32 transpose, [B][C][L] -> [B][L][C], tf32 out.
// ---------------------------------------------------------------------------
__global__ __launch_bounds__(256) void transpose_norm(const float* __restrict__ in,
                                                      const float2* __restrict__ st,
                                                      float* __restrict__ out)
{
    __shared__ float tile[32][33];
    int b = blockIdx.z;
    int l0 = blockIdx.x * 32, c0 = blockIdx.y * 32;
    int tx = threadIdx.x & 31, ty = threadIdx.x >> 5;
    #pragma unroll
    for (int i = 0; i < 4; i++) {
        int c = c0 + ty + i * 8;
        float2 f = st[b * C_ + c];
        float x = in[((size_t)(b * C_ + c)) * L_ + l0 + tx];
        tile[ty + i * 8][tx] = f2tf_f(fmaf(x, f.x, f.y));
    }
    __syncthreads();
    #pragma unroll
    for (int i = 0; i < 4; i++) {
        int l = l0 + ty + i * 8;
        out[((size_t)b * L_ + l) * C_ + c0 + tx] = tile[tx][ty + i * 8];
    }
}

// ---------------------------------------------------------------------------
// tf32 tensor-core GEMM — cp.async 2-stage pipeline, k-tile 32,
// FORCED 2 CTAs/SM via __launch_bounds__(256, 2).  (unchanged from R9 WIN)
// ---------------------------------------------------------------------------
constexpr int GEMM_SMEM = 2 * 2 * 128 * 36 * 4;   // 73728 B; x2 CTAs = 147 KB

template <int BIAS_MODE, bool RES, bool OTF32>
__global__ __launch_bounds__(256, 2) void gemm_tf32(
    const float* __restrict__ A, const float* __restrict__ Bm,
    const float* __restrict__ bias, const float* __restrict__ res,
    float* __restrict__ Cout, int K, int lda, int ldb, int ldc,
    float alpha, size_t strideA, size_t strideB, size_t strideC)
{
    extern __shared__ float smem[];
    float (*sA)[128][36] = (float(*)[128][36])smem;                    // [stage]
    float (*sB)[128][36] = (float(*)[128][36])(smem + 2 * 128 * 36);

    int bz = blockIdx.z;
    A  += strideA * bz;
    Bm += strideB * bz;

    int m0 = blockIdx.y * 128, n0 = blockIdx.x * 128;
    int tid = threadIdx.x, lane = tid & 31, w = tid >> 5;
    int wm = (w & 3) * 32, wn = (w >> 2) * 64;
    int g = lane >> 2, tg = lane & 3;

    int crow[4], cseg[4];
    #pragma unroll
    for (int it = 0; it < 4; it++) {
        int idx = tid + it * 256;
        crow[it] = idx >> 3;
        cseg[it] = (idx & 7) * 4;
    }

    float acc[2][8][4] = {};
    int KT = K / 32;

    #pragma unroll
    for (int it = 0; it < 4; it++) {
        CP_ASYNC16(smem_u32(&sA[0][crow[it]][cseg[it]]),
                   &A[(size_t)(m0 + crow[it]) * lda + cseg[it]]);
        CP_ASYNC16(smem_u32(&sB[0][crow[it]][cseg[it]]),
                   &Bm[(size_t)(n0 + crow[it]) * ldb + cseg[it]]);
    }
    CP_COMMIT();

    for (int kt = 0; kt < KT; kt++) {
        int st = kt & 1;
        if (kt + 1 < KT) {
            int k1 = (kt + 1) * 32, s1 = (kt + 1) & 1;
            #pragma unroll
            for (int it = 0; it < 4; it++) {
                CP_ASYNC16(smem_u32(&sA[s1][crow[it]][cseg[it]]),
                           &A[(size_t)(m0 + crow[it]) * lda + k1 + cseg[it]]);
                CP_ASYNC16(smem_u32(&sB[s1][crow[it]][cseg[it]]),
                           &Bm[(size_t)(n0 + crow[it]) * ldb + k1 + cseg[it]]);
            }
            CP_COMMIT();
            CP_WAIT1();
        } else {
            CP_WAIT0();
        }
        __syncthreads();

        #pragma unroll
        for (int ks = 0; ks < 4; ks++) {
            int kb = ks * 8 + tg;
            u32 afr[2][4], bfr[8][2];
            #pragma unroll
            for (int mt = 0; mt < 2; mt++) {
                int r = wm + mt * 16 + g;
                afr[mt][0] = __float_as_uint(sA[st][r][kb]);
                afr[mt][1] = __float_as_uint(sA[st][r + 8][kb]);
                afr[mt][2] = __float_as_uint(sA[st][r][kb + 4]);
                afr[mt][3] = __float_as_uint(sA[st][r + 8][kb + 4]);
            }
            #pragma unroll
            for (int nt = 0; nt < 8; nt++) {
                int c = wn + nt * 8 + g;
                bfr[nt][0] = __float_as_uint(sB[st][c][kb]);
                bfr[nt][1] = __float_as_uint(sB[st][c][kb + 4]);
            }
            #pragma unroll
            for (int mt = 0; mt < 2; mt++)
                #pragma unroll
                for (int nt = 0; nt < 8; nt++)
                    MMA_TF32(acc[mt][nt], afr[mt], bfr[nt]);
        }
        __syncthreads();
    }

    #pragma unroll
    for (int mt = 0; mt < 2; mt++) {
        #pragma unroll
        for (int half = 0; half < 2; half++) {
            int m = m0 + wm + mt * 16 + g + half * 8;
            float bm = (BIAS_MODE == 1) ? bias[m] : 0.f;
            #pragma unroll
            for (int nt = 0; nt < 8; nt++) {
                int n = n0 + wn + nt * 8 + tg * 2;
                float v0 = acc[mt][nt][half * 2 + 0] * alpha;
                float v1 = acc[mt][nt][half * 2 + 1] * alpha;
                if (BIAS_MODE == 1) { v0 += bm; v1 += bm; }
                if (BIAS_MODE == 2) { v0 += bias[n]; v1 += bias[n + 1]; }
                size_t off = strideC * bz + (size_t)m * ldc + n;
                if (RES) {
                    float2 r2 = *(const float2*)&res[off];
                    v0 += r2.x; v1 += r2.y;
                }
                if (OTF32) { v0 = f2tf_f(v0); v1 = f2tf_f(v1); }
                *(float2*)&Cout[off] = make_float2(v0, v1);
            }
        }
    }
}

// ---------------------------------------------------------------------------
// tf32 tensor-core 3-tap conv (implicit GEMM) — NOW cp.async 2-stage pipelined:
// raw input rows [16][144] + weight tiles double-buffered; patch built from
// smem (LDS) under the MMA shadow. 2 CTAs/SM forced.
// M=C (co), N=L(128-tile), K=768 in 16 chunks of 48 (16 ci x 3 taps).
// smem: 2*128*52 (W) + 2*16*144 (raw) + 128*52 (patch) floats = 96 KB.
// ---------------------------------------------------------------------------
constexpr int CONV_SMEM = (2 * 128 * 52 + 2 * 16 * 144 + 128 * 52) * 4;

template <bool ADDV, bool RES>
__global__ __launch_bounds__(256, 2) void conv_tf32(
    const float* __restrict__ in,   // [B][C][L] (tf32 values)
    const float* __restrict__ w,    // [C][768]  (tf32 values)
    const float* __restrict__ bias,
    const float* __restrict__ addv,
    const float* __restrict__ resid,
    float* __restrict__ out)
{
    extern __shared__ float smemc[];
    float (*sW)[128][52] = (float(*)[128][52])smemc;                 // [stage]
    float (*sR)[16][144] = (float(*)[16][144])(smemc + 2 * 128 * 52);
    float (*sP)[52]      = (float(*)[52])(smemc + 2 * 128 * 52 + 2 * 16 * 144);

    int b  = blockIdx.z;
    int m0 = blockIdx.y * 128;
    int l0 = blockIdx.x * 128;
    int tid = threadIdx.x, lane = tid & 31, wid = tid >> 5;
    int wm = (wid & 3) * 32, wn = (wid >> 2) * 64;
    int g = lane >> 2, tg = lane & 3;

    // issue one pipeline stage: weights (128x48) + raw rows (16 x [l0-8, l0+136))
    auto issue_stage = [&](int kt, int stg) {
        int k0 = kt * 48, ci0 = kt * 16;
        #pragma unroll
        for (int it = 0; it < 6; it++) {
            int idx = tid + it * 256;
            int row = idx / 12, seg = (idx % 12) * 4;
            CP_ASYNC16(smem_u32(&sW[stg][row][seg]),
                       &w[(size_t)(m0 + row) * 768 + k0 + seg]);
        }
        for (int idx = tid; idx < 16 * 36; idx += 256) {
            int c = idx / 36, ch = (idx % 36) * 4;
            int l = l0 - 8 + ch;
            if (l >= 0 && l + 3 < L_) {
                CP_ASYNC16(smem_u32(&sR[stg][c][ch]),
                           &in[((size_t)(b * C_ + ci0 + c)) * L_ + l]);
            } else {
                *(float4*)&sR[stg][c][ch] = make_float4(0.f, 0.f, 0.f, 0.f);
            }
        }
    };

    float acc[2][8][4] = {};

    issue_stage(0, 0);
    CP_COMMIT();

    for (int kt = 0; kt < 16; kt++) {
        int st = kt & 1;
        CP_WAIT0();
        __syncthreads();     // raw/w[st] arrived; all warps done with prev MMAs

        // build patch [l][3c+t] from raw (LDS, fast)
        for (int idx = tid; idx < 16 * 132; idx += 256) {
            int c = idx / 132, p = idx % 132;
            if (p < 130) {
                float v = sR[st][c][p + 7];   // raw idx 7 <=> l = l0-1
                #pragma unroll
                for (int t_ = 0; t_ < 3; t_++) {
                    int j = p - t_;
                    if (j >= 0 && j < 128) sP[j][3 * c + t_] = v;
                }
            }
        }
        if (kt + 1 < 16) { issue_stage(kt + 1, st ^ 1); CP_COMMIT(); }
        __syncthreads();     // patch ready; cp.async overlaps MMAs below

        #pragma unroll
        for (int ks = 0; ks < 6; ks++) {
            int kb = ks * 8 + tg;
            u32 afr[2][4], bfr[8][2];
            #pragma unroll
            for (int mt = 0; mt < 2; mt++) {
                int r = wm + mt * 16 + g;
                afr[mt][0] = __float_as_uint(sW[st][r][kb]);
                afr[mt][1] = __float_as_uint(sW[st][r + 8][kb]);
                afr[mt][2] = __float_as_uint(sW[st][r][kb + 4]);
                afr[mt][3] = __float_as_uint(sW[st][r + 8][kb + 4]);
            }
            #pragma unroll
            for (int nt = 0; nt < 8; nt++) {
                int c = wn + nt * 8 + g;
                bfr[nt][0] = __float_as_uint(sP[c][kb]);
                bfr[nt][1] = __float_as_uint(sP[c][kb + 4]);
            }
            #pragma unroll
            for (int mt = 0; mt < 2; mt++)
                #pragma unroll
                for (int nt = 0; nt < 8; nt++)
                    MMA_TF32(acc[mt][nt], afr[mt], bfr[nt]);
        }
    }

    #pragma unroll
    for (int mt = 0; mt < 2; mt++) {
        #pragma unroll
        for (int half = 0; half < 2; half++) {
            int m = m0 + wm + mt * 16 + g + half * 8;
            float base = bias[m];
            if (ADDV) base += addv[b * C_ + m];
            #pragma unroll
            for (int nt = 0; nt < 8; nt++) {
                int n = l0 + wn + nt * 8 + tg * 2;
                float v0 = acc[mt][nt][half * 2 + 0] + base;
                float v1 = acc[mt][nt][half * 2 + 1] + base;
                size_t off = ((size_t)(b * C_ + m)) * L_ + n;
                if (RES) {
                    float2 r2 = *(const float2*)&resid[off];
                    v0 += r2.x; v1 += r2.y;
                }
                *(float2*)&out[off] = make_float2(v0, v1);
            }
        }
    }
}

// ---------------------------------------------------------------------------
// Row softmax in-place, float4 vectorized, tf32-round on store.
// ---------------------------------------------------------------------------
__global__ __launch_bounds__(256) void softmax_kernel(float* __restrict__ w)
{
    __shared__ float red[8];
    __shared__ float red2[8];
    size_t row = blockIdx.x;
    float4* p4 = (float4*)(w + row * (size_t)L_);
    int tid = threadIdx.x;

    float4 a = p4[tid];
    float4 b = p4[tid + 256];
    float v[8] = { a.x, a.y, a.z, a.w, b.x, b.y, b.z, b.w };

    float mx = v[0];
    #pragma unroll
    for (int i = 1; i < 8; i++) mx = fmaxf(mx, v[i]);
    #pragma unroll
    for (int o = 16; o > 0; o >>= 1) mx = fmaxf(mx, __shfl_xor_sync(0xffffffffu, mx, o));
    if ((tid & 31) == 0) red[tid >> 5] = mx;
    __syncthreads();
    float m = red[0];
    #pragma unroll
    for (int i = 1; i < 8; i++) m = fmaxf(m, red[i]);

    float s = 0.f;
    #pragma unroll
    for (int i = 0; i < 8; i++) { v[i] = expf(v[i] - m); s += v[i]; }
    #pragma unroll
    for (int o = 16; o > 0; o >>= 1) s += __shfl_xor_sync(0xffffffffu, s, o);
    if ((tid & 31) == 0) red2[tid >> 5] = s;
    __syncthreads();
    float tot = 0.f;
    #pragma unroll
    for (int i = 0; i < 8; i++) tot += red2[i];
    float inv = 1.f / tot;

    float4 oa, ob;
    oa.x = f2tf_f(v[0] * inv); oa.y = f2tf_f(v[1] * inv);
    oa.z = f2tf_f(v[2] * inv); oa.w = f2tf_f(v[3] * inv);
    ob.x = f2tf_f(v[4] * inv); ob.y = f2tf_f(v[5] * inv);
    ob.z = f2tf_f(v[6] * inv); ob.w = f2tf_f(v[7] * inv);
    p4[tid]       = oa;
    p4[tid + 256] = ob;
}

// ---------------------------------------------------------------------------
// Host orchestration (graph-capturable: kernel launches only)
// ---------------------------------------------------------------------------
extern "C" void kernel_launch(void* const* d_in, const int* in_sizes, int n_in,
                              void* d_out, int out_size)
{
    (void)in_sizes; (void)n_in; (void)out_size;

    const float* x   = (const float*)d_in[0];
    const int*   t   = (const int*)  d_in[1];
    const float* z0  = (const float*)d_in[2];
    const float* zt  = (const float*)d_in[3];
    const float* tw1 = (const float*)d_in[4];
    const float* tb1 = (const float*)d_in[5];
    const float* tw2 = (const float*)d_in[6];
    const float* tb2 = (const float*)d_in[7];
    const float* tpw = (const float*)d_in[8];
    const float* tpb = (const float*)d_in[9];
    const float* zpw = (const float*)d_in[10];
    const float* zpb = (const float*)d_in[11];
    const float* n1g = (const float*)d_in[12];
    const float* n1b = (const float*)d_in[13];
    const float* n2g = (const float*)d_in[14];
    const float* n2b = (const float*)d_in[15];
    const float* ng  = (const float*)d_in[16];
    const float* nb  = (const float*)d_in[17];
    const float* c1w = (const float*)d_in[18];
    const float* c1b = (const float*)d_in[19];
    const float* c2w = (const float*)d_in[20];
    const float* c2b = (const float*)d_in[21];
    const float* qw  = (const float*)d_in[22];
    const float* qb  = (const float*)d_in[23];
    const float* kw  = (const float*)d_in[24];
    const float* kb  = (const float*)d_in[25];
    const float* vw  = (const float*)d_in[26];
    const float* vb  = (const float*)d_in[27];
    const float* pw  = (const float*)d_in[28];
    const float* pb  = (const float*)d_in[29];
    float* out = (float*)d_out;

    float *p_t1, *p_h, *p_x1, *p_hnT, *p_qk, *p_v, *p_h2T, *p_sc, *p_add, *p_wr;
    float2* p_st;
    cudaGetSymbolAddress((void**)&p_t1,  g_t1);
    cudaGetSymbolAddress((void**)&p_h,   g_h);
    cudaGetSymbolAddress((void**)&p_x1,  g_x1);
    cudaGetSymbolAddress((void**)&p_hnT, g_hnT);
    cudaGetSymbolAddress((void**)&p_qk,  g_qk);
    cudaGetSymbolAddress((void**)&p_v,   g_v);
    cudaGetSymbolAddress((void**)&p_h2T, g_h2T);
    cudaGetSymbolAddress((void**)&p_sc,  g_sc);
    cudaGetSymbolAddress((void**)&p_add, g_add);
    cudaGetSymbolAddress((void**)&p_wr,  g_wr);
    cudaGetSymbolAddress((void**)&p_st,  g_st);

    float* wr_qk  = p_wr;                                    // [512][256]
    float* wr_v   = p_wr + 512 * C_;                         // [256][256]
    float* wr_p   = wr_v + C_ * C_;                          // [256][256]
    float* wr_c1  = wr_p + C_ * C_;                          // [256][768]
    float* wr_c2  = wr_c1 + C_ * C_ * 3;                     // [256][768]
    float* b_qk   = wr_c2 + C_ * C_ * 3;                     // [512]

    // dynamic-smem attributes (host-side, idempotent)
    cudaFuncSetAttribute(gemm_tf32<2, false, true>,
                         cudaFuncAttributeMaxDynamicSharedMemorySize, GEMM_SMEM);
    cudaFuncSetAttribute(gemm_tf32<1, false, true>,
                         cudaFuncAttributeMaxDynamicSharedMemorySize, GEMM_SMEM);
    cudaFuncSetAttribute(gemm_tf32<0, false, false>,
                         cudaFuncAttributeMaxDynamicSharedMemorySize, GEMM_SMEM);
    cudaFuncSetAttribute(gemm_tf32<0, false, true>,
                         cudaFuncAttributeMaxDynamicSharedMemorySize, GEMM_SMEM);
    cudaFuncSetAttribute(gemm_tf32<1, true, false>,
                         cudaFuncAttributeMaxDynamicSharedMemorySize, GEMM_SMEM);
    cudaFuncSetAttribute(conv_tf32<true, false>,
                         cudaFuncAttributeMaxDynamicSharedMemorySize, CONV_SMEM);
    cudaFuncSetAttribute(conv_tf32<false, true>,
                         cudaFuncAttributeMaxDynamicSharedMemorySize, CONV_SMEM);

    const size_t sCL  = (size_t)C_ * L_;    // [B,C,L] / [B,L,C] batch stride
    const size_t sQK  = (size_t)L_ * 512;   // [B,L,512] batch stride
    const size_t sLL  = (size_t)L_ * L_;    // [B,L,L] batch stride

    dim3 gconv(L_ / 128, C_ / 128, B_);

    // weight prep + temb
    round_tf32_kernel<<<(C_ * C_ * 3 + 255) / 256, 256>>>(c1w, wr_c1, C_ * C_ * 3);
    round_tf32_kernel<<<(C_ * C_ * 3 + 255) / 256, 256>>>(c2w, wr_c2, C_ * C_ * 3);
    temb_kernel<<<B_, 512>>>(t, z0, zt, tw1, tb1, tw2, tb2, tpw, tpb, zpw, zpb);
    round_concat_qk<<<(512 * C_ + 255) / 256, 256>>>(qw, kw, qb, kb, wr_qk, b_qk);
    round_tf32_kernel<<<(C_ * C_ + 255) / 256, 256>>>(vw, wr_v, C_ * C_);
    round_tf32_kernel<<<(C_ * C_ + 255) / 256, 256>>>(pw, wr_p, C_ * C_);

    // stage 1: t1 = tf32(silu(chan_norm(x, n1))); h = conv1(t1) + add
    norm_kernel<<<B_ * C_, 256>>>(x, p_t1, n1g, n1b);
    conv_tf32<true, false><<<gconv, 256, CONV_SMEM>>>(p_t1, wr_c1, c1b,
                                                      p_add, nullptr, p_h);

    // stage 2: t1 = tf32(silu(chan_norm(h, n2))); x1 = x + conv2(t1)
    norm_kernel<<<B_ * C_, 256>>>(p_h, p_t1, n2g, n2b);
    conv_tf32<false, true><<<gconv, 256, CONV_SMEM>>>(p_t1, wr_c2, c2b,
                                                      nullptr, x, p_x1);

    // stage 3: stats(x1, n) -> fused norm+transpose -> hnT [B][L][C] tf32
    stats_kernel<<<B_ * C_, 256>>>(p_x1, ng, nb, p_st);
    dim3 gtr(L_ / 32, C_ / 32, B_);
    transpose_norm<<<gtr, 256>>>(p_x1, p_st, p_hnT);

    // qk [L][512] = hnT @ [qw;kw]^T + b(per-n)    M=L, N=512, K=256
    dim3 gqk(512 / 128, L_ / 128, B_);
    gemm_tf32<2, false, true><<<gqk, 256, GEMM_SMEM>>>(
        p_hnT, wr_qk, b_qk, nullptr, p_qk,
        C_, C_, C_, 512, 1.f, sCL, 0, sQK);
    // v [C][L] = vw @ hn + b(per-m)               M=C, N=L, K=256
    dim3 gv(L_ / 128, C_ / 128, B_);
    gemm_tf32<1, false, true><<<gv, 256, GEMM_SMEM>>>(
        wr_v, p_hnT, vb, nullptr, p_v,
        C_, C_, C_, L_, 1.f, 0, sCL, sCL);

    // scores[i][j] = (1/16) q[i]·k[j]             M=N=L, K=256 (ld 512)
    dim3 gsc(L_ / 128, L_ / 128, B_);
    gemm_tf32<0, false, false><<<gsc, 256, GEMM_SMEM>>>(
        p_qk, p_qk + 256, nullptr, nullptr, p_sc,
        C_, 512, 512, L_, 0.0625f, sQK, sQK, sLL);

    // softmax over j (in place, tf32 out)
    softmax_kernel<<<B_ * L_, 256>>>(p_sc);

    // h2T[i][c] = sum_j sc[i][j] v[c][j]          M=L, N=C, K=L
    dim3 gh2(C_ / 128, L_ / 128, B_);
    gemm_tf32<0, false, true><<<gh2, 256, GEMM_SMEM>>>(
        p_sc, p_v, nullptr, nullptr, p_h2T,
        L_, L_, L_, C_, 1.f, sLL, sCL, sCL);

    // out[c][l] = pw @ h2 + pb + x1               M=C, N=L, K=256
    dim3 gpr(L_ / 128, C_ / 128, B_);
    gemm_tf32<1, true, false><<<gpr, 256, GEMM_SMEM>>>(
        wr_p, p_h2T, pb, p_x1, out,
        C_, C_, C_, L_, 1.f, 0, sCL, sCL);
}